// round 2
// baseline (speedup 1.0000x reference)
#include <cuda_runtime.h>
#include <cstdint>
#include <math.h>

// ===========================================================================
// LangVisNet: D=10000 EMB=1000 HID=1000 VIS=2688 MIX=1000 HMIX=1005 T=8 H=W=16
//
// Pipeline:
//   le = emb[lang]                                   (k_embed)
//   lo1 = LSTM(le)   lo = LSTM(lo1)                  (gemm pre + k_scan) x2
//   filt = sigmoid(lo @ afW^T + afb)                 (k_filt)
//   p[t,hw] = sum_c filt[t,c] visxy[c,hw]            (k_p)
//   qbase[hw,m] = sum_c ccW[m,c] visxy[c,hw]         (gemm)
//   qlang[t,m]  = sum_e ccW[m,2690+e] le + ccW[m,3690+e] lo   (k_qlang)
//   PB[hw,r] = Wih0 . qbase ; PL[t,r] = Wih0 . qlang (gemm)
//   wp[r] = Wih0 . ccW[:,4690]; pc[r]=Wih0.ccb+bias  (k_wp)
//   pre1[s,r] = PB + PL + wp*p + pc  (s = hw*8+t)    (k_pre1)
//   h1 = scan(pre1, Whh0); pre2 = WihR0.h1 + b       (k_scan / gemm)
//   h2 = scan(pre2, Whh1); pre3 = WihR1.h2 + b
//   h3 = scan(pre3, Whh2)
//   out[j] = ocW . h3[1792+j] + ocb                  (k_out)
// ===========================================================================

#define KPAD 1024
#define HSTR 1008   // padded row stride for h sequences (mult of 4)

// ------------------------- device scratch ----------------------------------
__device__ __align__(16) float g_visxy [2690 * 256];
__device__ __align__(16) float g_visxyT[256 * 2690];
__device__ __align__(16) float g_le    [8 * 1000];
__device__ __align__(16) float g_hl1   [8 * 1000];
__device__ __align__(16) float g_lo    [8 * 1000];
__device__ __align__(16) float g_filt  [8 * 2690];
__device__ __align__(16) float g_p     [8 * 256];
__device__ __align__(16) float g_qlang [8 * 1000];
__device__ __align__(16) float g_qbase [256 * 1000];
__device__ __align__(16) float g_PB    [256 * 4020];
__device__ __align__(16) float g_PL    [8 * 4020];
__device__ __align__(16) float g_wp    [4020];
__device__ __align__(16) float g_pc    [4020];
__device__ __align__(16) float g_pre   [2048u * 4020u];
__device__ __align__(16) float g_h1    [2048 * HSTR];
__device__ __align__(16) float g_h2    [2048 * HSTR];
__device__ __align__(16) float g_h3    [2048 * HSTR];
__device__ __align__(16) float g_hbuf  [2048];
__device__                unsigned g_cnt[8];

// ------------------------------ helpers ------------------------------------
__device__ __forceinline__ float wred(float a) {
#pragma unroll
    for (int o = 16; o > 0; o >>= 1) a += __shfl_down_sync(0xffffffffu, a, o);
    return a;
}

// ------------------------------ init ---------------------------------------
__global__ void k_init() {
    if (threadIdx.x < 8) g_cnt[threadIdx.x] = 0u;
}

// --------------------------- vis_xy build ----------------------------------
__global__ void k_visxy(const float* __restrict__ vis) {
    int c = blockIdx.x, hw = threadIdx.x;
    float v;
    if (c < 2688)       v = vis[c * 256 + hw];
    else if (c == 2688) v = -1.f + (2.f / 15.f) * (float)(hw & 15);   // xs[w]
    else                v = -1.f + (2.f / 15.f) * (float)(hw >> 4);   // ys[h]
    g_visxy[c * 256 + hw]  = v;
    g_visxyT[hw * 2690 + c] = v;
}

// ------------------------------ embedding ----------------------------------
__global__ void k_embed(const int* __restrict__ lang, const float* __restrict__ emb) {
    int t = blockIdx.x;
    const float* src = emb + (size_t)lang[t] * 1000;
    for (int e = threadIdx.x; e < 1000; e += blockDim.x)
        g_le[t * 1000 + e] = src[e];
}

// ---------------------- persistent LSTM scan --------------------------------
// CTA b owns hidden units [8b, 8b+8). SMEM: 32 weight rows (4 gates x 8 units)
// padded to KPAD cols. Warp w handles unit j0+w; lane-strided dot + shfl reduce.
// Grid-wide step barrier: monotonic counter, red.release / ld.acquire.
__global__ void __launch_bounds__(256, 1) k_scan(
    const float* __restrict__ pre,   // T x (4*Hn)
    const float* __restrict__ Whh,   // (4*Hn) x Hn
    float* __restrict__ hseq, int hstride,
    unsigned* __restrict__ cnt, int T, int Hn)
{
    extern __shared__ float wsm[];
    const int tid = threadIdx.x;
    const int warp = tid >> 5, lane = tid & 31;
    const int j0 = blockIdx.x * 8;
    const int R = 4 * Hn;

    // load weights into SMEM (zero-padded)
    for (int row = warp; row < 32; row += 8) {
        int g = row >> 3, u = row & 7;
        int j = j0 + u;
        float* dst = wsm + row * KPAD;
        if (j < Hn) {
            const float* src = Whh + (size_t)(g * Hn + j) * Hn;
            for (int k = lane; k < KPAD; k += 32) dst[k] = (k < Hn) ? src[k] : 0.f;
        } else {
            for (int k = lane; k < KPAD; k += 32) dst[k] = 0.f;
        }
    }
    __syncthreads();

    const int j = j0 + warp;
    const bool jv = (j < Hn);
    const float* wA = wsm + (0 * 8 + warp) * KPAD;
    const float* wB = wsm + (1 * 8 + warp) * KPAD;
    const float* wC = wsm + (2 * 8 + warp) * KPAD;
    const float* wD = wsm + (3 * 8 + warp) * KPAD;
    float c = 0.f;
    const unsigned NC = gridDim.x;

    for (int s = 0; s < T; s++) {
        float4 h4[8];
        if (s > 0) {
            if (tid == 0) {
                unsigned target = NC * (unsigned)s;
                unsigned v;
                do {
                    asm volatile("ld.acquire.gpu.global.u32 %0, [%1];"
                                 : "=r"(v) : "l"(cnt) : "memory");
                } while (v < target);
            }
            __syncthreads();
            const float4* hp = (const float4*)(g_hbuf + ((s - 1) & 1) * 1024);
#pragma unroll
            for (int k = 0; k < 8; k++) h4[k] = hp[k * 32 + lane];
        } else {
#pragma unroll
            for (int k = 0; k < 8; k++) h4[k] = make_float4(0.f, 0.f, 0.f, 0.f);
        }

        float p0 = 0.f, p1 = 0.f, p2 = 0.f, p3 = 0.f;
        if (lane == 0 && jv) {
            const float* pr = pre + (size_t)s * R + j;
            p0 = pr[0]; p1 = pr[Hn]; p2 = pr[2 * Hn]; p3 = pr[3 * Hn];
        }

        float a0 = 0.f, a1 = 0.f, a2 = 0.f, a3 = 0.f;
#pragma unroll
        for (int k = 0; k < 8; k++) {
            int idx = k * 128 + lane * 4;
            float4 h = h4[k];
            float4 w;
            w = *(const float4*)(wA + idx);
            a0 += w.x * h.x; a0 += w.y * h.y; a0 += w.z * h.z; a0 += w.w * h.w;
            w = *(const float4*)(wB + idx);
            a1 += w.x * h.x; a1 += w.y * h.y; a1 += w.z * h.z; a1 += w.w * h.w;
            w = *(const float4*)(wC + idx);
            a2 += w.x * h.x; a2 += w.y * h.y; a2 += w.z * h.z; a2 += w.w * h.w;
            w = *(const float4*)(wD + idx);
            a3 += w.x * h.x; a3 += w.y * h.y; a3 += w.z * h.z; a3 += w.w * h.w;
        }
        a0 = wred(a0); a1 = wred(a1); a2 = wred(a2); a3 = wred(a3);

        if (lane == 0 && jv) {
            float gi = a0 + p0, gf = a1 + p1, gg = a2 + p2, go = a3 + p3;
            float si = 1.f / (1.f + expf(-gi));
            float sf = 1.f / (1.f + expf(-gf));
            float so = 1.f / (1.f + expf(-go));
            c = sf * c + si * tanhf(gg);
            float h = so * tanhf(c);
            g_hbuf[(s & 1) * 1024 + j] = h;
            hseq[(size_t)s * hstride + j] = h;
        }
        __syncthreads();
        if (tid == 0)
            asm volatile("red.release.gpu.global.add.u32 [%0], %1;"
                         :: "l"(cnt), "r"(1u) : "memory");
    }
}

// ------------------------------ generic GEMM --------------------------------
// C[n][m] = sum_k A[m][k] * B[n][k] (+ b1[m] + b2[m]);  A: MxK lda, B: NxK ldb
__device__ __forceinline__ float4 ldg4(const float* __restrict__ base,
                                       int r, int cc, int Rm, int K, int ld) {
    float4 v = make_float4(0.f, 0.f, 0.f, 0.f);
    if (r < Rm) {
        const float* p = base + (size_t)r * ld + cc;
        size_t off = (size_t)r * ld + cc;
        if (cc + 3 < K && ((off & 3u) == 0)) {
            v = *(const float4*)p;
        } else {
            if (cc     < K) v.x = p[0];
            if (cc + 1 < K) v.y = p[1];
            if (cc + 2 < K) v.z = p[2];
            if (cc + 3 < K) v.w = p[3];
        }
    }
    return v;
}

__global__ void __launch_bounds__(256) k_gemm(
    const float* __restrict__ A, const float* __restrict__ B,
    float* __restrict__ C, const float* __restrict__ b1, const float* __restrict__ b2,
    int M, int N, int K, int lda, int ldb, int ldc)
{
    __shared__ __align__(16) float As[16][68];
    __shared__ __align__(16) float Bs[16][68];
    int tid = threadIdx.x;
    int m0 = blockIdx.x * 64, n0 = blockIdx.y * 64;
    int lr = tid >> 2, lc = (tid & 3) * 4;
    int tx = tid & 15, ty = tid >> 4;
    float acc[4][4];
#pragma unroll
    for (int i = 0; i < 4; i++)
#pragma unroll
        for (int jj = 0; jj < 4; jj++) acc[i][jj] = 0.f;

    for (int k0 = 0; k0 < K; k0 += 16) {
        float4 a4 = ldg4(A, m0 + lr, k0 + lc, M, K, lda);
        float4 b4 = ldg4(B, n0 + lr, k0 + lc, N, K, ldb);
        As[lc + 0][lr] = a4.x; As[lc + 1][lr] = a4.y;
        As[lc + 2][lr] = a4.z; As[lc + 3][lr] = a4.w;
        Bs[lc + 0][lr] = b4.x; Bs[lc + 1][lr] = b4.y;
        Bs[lc + 2][lr] = b4.z; Bs[lc + 3][lr] = b4.w;
        __syncthreads();
#pragma unroll
        for (int kk = 0; kk < 16; kk++) {
            float4 a = *(const float4*)&As[kk][ty * 4];
            float4 b = *(const float4*)&Bs[kk][tx * 4];
            acc[0][0] += b.x * a.x; acc[0][1] += b.x * a.y; acc[0][2] += b.x * a.z; acc[0][3] += b.x * a.w;
            acc[1][0] += b.y * a.x; acc[1][1] += b.y * a.y; acc[1][2] += b.y * a.z; acc[1][3] += b.y * a.w;
            acc[2][0] += b.z * a.x; acc[2][1] += b.z * a.y; acc[2][2] += b.z * a.z; acc[2][3] += b.z * a.w;
            acc[3][0] += b.w * a.x; acc[3][1] += b.w * a.y; acc[3][2] += b.w * a.z; acc[3][3] += b.w * a.w;
        }
        __syncthreads();
    }

    int mb = m0 + ty * 4;
    float bb[4];
#pragma unroll
    for (int im = 0; im < 4; im++) {
        int m = mb + im;
        bb[im] = (m < M) ? ((b1 ? b1[m] : 0.f) + (b2 ? b2[m] : 0.f)) : 0.f;
    }
#pragma unroll
    for (int jn = 0; jn < 4; jn++) {
        int n = n0 + tx * 4 + jn;
        if (n >= N) continue;
        if (mb + 3 < M) {
            float4 v = make_float4(acc[jn][0] + bb[0], acc[jn][1] + bb[1],
                                   acc[jn][2] + bb[2], acc[jn][3] + bb[3]);
            *(float4*)&C[(size_t)n * ldc + mb] = v;
        } else {
#pragma unroll
            for (int im = 0; im < 4; im++) {
                int m = mb + im;
                if (m < M) C[(size_t)n * ldc + m] = acc[jn][im] + bb[im];
            }
        }
    }
}

// ------------------------------ filt ---------------------------------------
__global__ void k_filt(const float* __restrict__ afW, const float* __restrict__ afb) {
    __shared__ float w[1000];
    int cc = blockIdx.x;
    for (int e = threadIdx.x; e < 1000; e += 256) w[e] = afW[(size_t)cc * 1000 + e];
    __syncthreads();
    int t = threadIdx.x >> 5, lane = threadIdx.x & 31;
    float a = 0.f;
    for (int e = lane; e < 1000; e += 32) a += w[e] * g_lo[t * 1000 + e];
    a = wred(a);
    if (lane == 0)
        g_filt[t * 2690 + cc] = 1.f / (1.f + expf(-(a + afb[cc])));
}

// ------------------------------ p ------------------------------------------
__global__ void k_p() {
    int t = blockIdx.x, hw = threadIdx.x;
    const float* f = g_filt + t * 2690;
    float a0 = 0.f, a1 = 0.f;
    for (int cc = 0; cc < 2690; cc += 2) {
        a0 += f[cc] * g_visxy[cc * 256 + hw];
        a1 += f[cc + 1] * g_visxy[(cc + 1) * 256 + hw];
    }
    g_p[t * 256 + hw] = a0 + a1;
}

// ------------------------------ qlang --------------------------------------
__global__ void k_qlang(const float* __restrict__ ccW) {
    int m = blockIdx.x;
    int t = threadIdx.x >> 5, lane = threadIdx.x & 31;
    const float* row = ccW + (size_t)m * 4691;
    float a = 0.f;
    for (int e = lane; e < 1000; e += 32)
        a += row[2690 + e] * g_le[t * 1000 + e] + row[3690 + e] * g_lo[t * 1000 + e];
    a = wred(a);
    if (lane == 0) g_qlang[t * 1000 + m] = a;
}

// ------------------------------ wp / pc ------------------------------------
__global__ void k_wp(const float* __restrict__ Wih0, const float* __restrict__ ccW,
                     const float* __restrict__ ccb, const float* __restrict__ bih,
                     const float* __restrict__ bhh) {
    int r = blockIdx.x * 8 + (threadIdx.x >> 5);
    int lane = threadIdx.x & 31;
    if (r >= 4020) return;
    const float* Wr = Wih0 + (size_t)r * 1000;
    float aw = 0.f, ac = 0.f;
    for (int m = lane; m < 1000; m += 32) {
        float wv = Wr[m];
        aw += wv * ccW[(size_t)m * 4691 + 4690];
        ac += wv * ccb[m];
    }
    aw = wred(aw); ac = wred(ac);
    if (lane == 0) {
        g_wp[r] = aw;
        g_pc[r] = ac + bih[r] + bhh[r];
    }
}

// ------------------------------ pre1 assembly -------------------------------
__global__ void k_pre1() {
    int s = blockIdx.x;
    int t = s & 7, hw = s >> 3;
    float pv = g_p[t * 256 + hw];
    const float* pb = g_PB + (size_t)hw * 4020;
    const float* pl = g_PL + t * 4020;
    float* dst = g_pre + (size_t)s * 4020;
    for (int r = threadIdx.x; r < 4020; r += 256)
        dst[r] = pb[r] + pl[r] + g_wp[r] * pv + g_pc[r];
}

// ------------------------------ out ----------------------------------------
__global__ void k_out(const float* __restrict__ ocW, const float* __restrict__ ocb,
                      float* __restrict__ out) {
    int j = blockIdx.x * 8 + (threadIdx.x >> 5);
    int lane = threadIdx.x & 31;
    const float* h = g_h3 + (size_t)(1792 + j) * HSTR;
    float a = 0.f;
    for (int cc = lane; cc < 1005; cc += 32) a += ocW[cc] * h[cc];
    a = wred(a);
    if (lane == 0) out[j] = a + ocb[0];
}

// ===========================================================================
extern "C" void kernel_launch(void* const* d_in, const int* in_sizes, int n_in,
                              void* d_out, int out_size) {
    const float* vis   = (const float*)d_in[0];
    const int*   lang  = (const int*)  d_in[1];
    const float* emb   = (const float*)d_in[2];
    const float* lWih  = (const float*)d_in[3];
    const float* lWhh  = (const float*)d_in[4];
    const float* lbih  = (const float*)d_in[5];
    const float* lbhh  = (const float*)d_in[6];
    const float* mWih0 = (const float*)d_in[7];
    const float* mWihR = (const float*)d_in[8];
    const float* mWhh  = (const float*)d_in[9];
    const float* mbih  = (const float*)d_in[10];
    const float* mbhh  = (const float*)d_in[11];
    const float* afW   = (const float*)d_in[12];
    const float* afb   = (const float*)d_in[13];
    const float* ccW   = (const float*)d_in[14];
    const float* ccb   = (const float*)d_in[15];
    const float* ocW   = (const float*)d_in[16];
    const float* ocb   = (const float*)d_in[17];
    float* out = (float*)d_out;

    cudaFuncSetAttribute(k_scan, cudaFuncAttributeMaxDynamicSharedMemorySize, 131072);

    float *pre_, *hl1_, *lo_, *qlang_, *qbase_, *PB_, *PL_, *visT_, *h1_, *h2_, *h3_;
    unsigned* cnt_;
    cudaGetSymbolAddress((void**)&pre_,   g_pre);
    cudaGetSymbolAddress((void**)&hl1_,   g_hl1);
    cudaGetSymbolAddress((void**)&lo_,    g_lo);
    cudaGetSymbolAddress((void**)&qlang_, g_qlang);
    cudaGetSymbolAddress((void**)&qbase_, g_qbase);
    cudaGetSymbolAddress((void**)&PB_,    g_PB);
    cudaGetSymbolAddress((void**)&PL_,    g_PL);
    cudaGetSymbolAddress((void**)&visT_,  g_visxyT);
    cudaGetSymbolAddress((void**)&h1_,    g_h1);
    cudaGetSymbolAddress((void**)&h2_,    g_h2);
    cudaGetSymbolAddress((void**)&h3_,    g_h3);
    cudaGetSymbolAddress((void**)&cnt_,   g_cnt);

    auto gemm = [](const float* A, const float* B, float* C,
                   const float* b1, const float* b2,
                   int M, int N, int K, int lda, int ldb, int ldc) {
        dim3 g((M + 63) / 64, (N + 63) / 64);
        k_gemm<<<g, 256>>>(A, B, C, b1, b2, M, N, K, lda, ldb, ldc);
    };

    k_init<<<1, 32>>>();
    k_visxy<<<2690, 256>>>(vis);
    k_embed<<<8, 256>>>(lang, emb);

    // ---- language LSTM (2 layers, T=8, Hn=1000) ----
    float *le_; cudaGetSymbolAddress((void**)&le_, g_le);
    gemm(lWih, le_, pre_, lbih, lbhh, 4000, 8, 1000, 1000, 1000, 4000);
    k_scan<<<125, 256, 131072>>>(pre_, lWhh, hl1_, 1000, cnt_ + 0, 8, 1000);
    gemm(lWih + 4000000, hl1_, pre_, lbih + 4000, lbhh + 4000, 4000, 8, 1000, 1000, 1000, 4000);
    k_scan<<<125, 256, 131072>>>(pre_, lWhh + 4000000, lo_, 1000, cnt_ + 1, 8, 1000);

    // ---- attention filter + q decomposition ----
    k_filt<<<2690, 256>>>(afW, afb);
    k_p<<<8, 256>>>();
    k_qlang<<<1000, 256>>>(ccW);
    gemm(ccW, visT_, qbase_, nullptr, nullptr, 1000, 256, 2690, 4691, 2690, 1000);
    gemm(mWih0, qbase_, PB_, nullptr, nullptr, 4020, 256, 1000, 1000, 1000, 4020);
    gemm(mWih0, qlang_, PL_, nullptr, nullptr, 4020, 8, 1000, 1000, 1000, 4020);
    k_wp<<<503, 256>>>(mWih0, ccW, ccb, mbih, mbhh);
    k_pre1<<<2048, 256>>>();

    // ---- mRNN (3 layers, T=2048, Hn=1005) ----
    k_scan<<<126, 256, 131072>>>(pre_, mWhh, h1_, HSTR, cnt_ + 2, 2048, 1005);
    gemm(mWihR, h1_, pre_, mbih + 4020, mbhh + 4020, 4020, 2048, 1005, 1005, HSTR, 4020);
    k_scan<<<126, 256, 131072>>>(pre_, mWhh + (size_t)4020 * 1005, h2_, HSTR, cnt_ + 3, 2048, 1005);
    gemm(mWihR + (size_t)4020 * 1005, h2_, pre_, mbih + 8040, mbhh + 8040, 4020, 2048, 1005, 1005, HSTR, 4020);
    k_scan<<<126, 256, 131072>>>(pre_, mWhh + (size_t)2 * 4020 * 1005, h3_, HSTR, cnt_ + 4, 2048, 1005);

    // ---- final projection ----
    k_out<<<32, 256>>>(ocW, ocb, out);
}

// round 4
// speedup vs baseline: 1.2452x; 1.2452x over previous
#include <cuda_runtime.h>
#include <cstdint>
#include <math.h>

// ===========================================================================
// LangVisNet: D=10000 EMB=1000 HID=1000 VIS=2688 MIX=1000 HMIX=1005 T=8 H=W=16
// ===========================================================================

#define HSTR 1008   // padded row stride for h sequences (mult of 4)
#define PCH  22     // k_p partial chunks

// ------------------------- device scratch ----------------------------------
__device__ __align__(16) float g_visxy [2690 * 256];
__device__ __align__(16) float g_visxyT[256 * 2690];
__device__ __align__(16) float g_le    [8 * 1000];
__device__ __align__(16) float g_hl1   [8 * 1000];
__device__ __align__(16) float g_lo    [8 * 1000];
__device__ __align__(16) float g_filt  [8 * 2690];
__device__ __align__(16) float g_ppart [PCH * 8 * 256];
__device__ __align__(16) float g_p     [8 * 256];
__device__ __align__(16) float g_qlang [8 * 1000];
__device__ __align__(16) float g_qbase [256 * 1000];
__device__ __align__(16) float g_PB    [256 * 4020];
__device__ __align__(16) float g_PL    [8 * 4020];
__device__ __align__(16) float g_wp    [4020];
__device__ __align__(16) float g_pc    [4020];
__device__ __align__(16) float g_pre   [2048u * 4020u];
__device__ __align__(16) float g_h1    [2048 * HSTR];
__device__ __align__(16) float g_h2    [2048 * HSTR];
__device__ __align__(16) float g_h3    [2048 * HSTR];
__device__ __align__(16) float g_hbuf  [2048];
__device__                unsigned g_cnt[8];

// ------------------------------ helpers ------------------------------------
__device__ __forceinline__ float wred(float a) {
#pragma unroll
    for (int o = 16; o > 0; o >>= 1) a += __shfl_down_sync(0xffffffffu, a, o);
    return a;
}

// ------------------------------ init ---------------------------------------
__global__ void k_init() {
    if (threadIdx.x < 8) g_cnt[threadIdx.x] = 0u;
}

// --------------------------- vis_xy build ----------------------------------
__global__ void k_visxy(const float* __restrict__ vis) {
    int c = blockIdx.x, hw = threadIdx.x;
    float v;
    if (c < 2688)       v = vis[c * 256 + hw];
    else if (c == 2688) v = -1.f + (2.f / 15.f) * (float)(hw & 15);   // xs[w]
    else                v = -1.f + (2.f / 15.f) * (float)(hw >> 4);   // ys[h]
    g_visxy[c * 256 + hw]   = v;
    g_visxyT[hw * 2690 + c] = v;
}

// ------------------------------ embedding ----------------------------------
__global__ void k_embed(const int* __restrict__ lang, const float* __restrict__ emb) {
    int t = blockIdx.x;
    const float* src = emb + (size_t)lang[t] * 1000;
    for (int e = threadIdx.x; e < 1000; e += blockDim.x)
        g_le[t * 1000 + e] = src[e];
}

// ---------------- persistent LSTM scan, register-resident weights ----------
// CTA b owns hidden units [8b, 8b+8); warp w handles unit 8b+w (4 gate rows).
// Each lane keeps 4 rows x 32 weight floats in REGISTERS for the whole scan.
// h(t-1) comes from a double-buffered global vector; a monotonic
// release/acquire counter forms the grid step barrier (tid0 polls).
__global__ void __launch_bounds__(256, 1) k_scan(
    const float* __restrict__ pre,   // T x (4*Hn)
    const float* __restrict__ Whh,   // (4*Hn) x Hn
    float* __restrict__ hseq, int hstride,
    unsigned* __restrict__ cnt, int T, int Hn)
{
    const int tid  = threadIdx.x;
    const int warp = tid >> 5, lane = tid & 31;
    const int j    = blockIdx.x * 8 + warp;   // hidden unit owned by this warp
    const bool jv  = (j < Hn);
    const unsigned NC = gridDim.x;

    // ---- load weights into registers (zero-padded to 1024 cols) ----
    // wreg[g][k*4 + e] multiplies h[k*128 + lane*4 + e]
    float wreg[4][32];
#pragma unroll
    for (int g = 0; g < 4; g++) {
        const float* src = Whh + (size_t)(g * Hn + j) * Hn;
#pragma unroll
        for (int k = 0; k < 8; k++) {
            int e = k * 128 + lane * 4;
            float f0 = 0.f, f1 = 0.f, f2 = 0.f, f3 = 0.f;
            if (jv) {
                if (e     < Hn) f0 = src[e];
                if (e + 1 < Hn) f1 = src[e + 1];
                if (e + 2 < Hn) f2 = src[e + 2];
                if (e + 3 < Hn) f3 = src[e + 3];
            }
            wreg[g][k * 4]     = f0;
            wreg[g][k * 4 + 1] = f1;
            wreg[g][k * 4 + 2] = f2;
            wreg[g][k * 4 + 3] = f3;
        }
    }

    float c = 0.f;
    for (int s = 0; s < T; s++) {
        // prefetch pre-activations (independent of h)
        float p0 = 0.f, p1 = 0.f, p2 = 0.f, p3 = 0.f;
        if (lane == 0 && jv) {
            const float* pr = pre + (size_t)s * 4 * Hn + j;
            p0 = pr[0]; p1 = pr[Hn]; p2 = pr[2 * Hn]; p3 = pr[3 * Hn];
        }

        float a0 = 0.f, a1 = 0.f, a2 = 0.f, a3 = 0.f;
        if (s > 0) {
            if (tid == 0) {
                unsigned target = NC * (unsigned)s;
                unsigned v;
                do {
                    asm volatile("ld.acquire.gpu.global.u32 %0, [%1];"
                                 : "=r"(v) : "l"(cnt) : "memory");
                } while (v < target);
            }
            __syncthreads();
            const float4* hp = (const float4*)(g_hbuf + ((s - 1) & 1) * 1024);
#pragma unroll
            for (int k = 0; k < 8; k++) {
                float4 h = hp[k * 32 + lane];
                a0 += wreg[0][k*4]*h.x; a0 += wreg[0][k*4+1]*h.y;
                a0 += wreg[0][k*4+2]*h.z; a0 += wreg[0][k*4+3]*h.w;
                a1 += wreg[1][k*4]*h.x; a1 += wreg[1][k*4+1]*h.y;
                a1 += wreg[1][k*4+2]*h.z; a1 += wreg[1][k*4+3]*h.w;
                a2 += wreg[2][k*4]*h.x; a2 += wreg[2][k*4+1]*h.y;
                a2 += wreg[2][k*4+2]*h.z; a2 += wreg[2][k*4+3]*h.w;
                a3 += wreg[3][k*4]*h.x; a3 += wreg[3][k*4+1]*h.y;
                a3 += wreg[3][k*4+2]*h.z; a3 += wreg[3][k*4+3]*h.w;
            }
        }
        // s==0: h=0 -> gate contributions are 0; skip the dot entirely.

        a0 = wred(a0); a1 = wred(a1); a2 = wred(a2); a3 = wred(a3);

        if (lane == 0 && jv) {
            float gi = a0 + p0, gf = a1 + p1, gg = a2 + p2, go = a3 + p3;
            float si = 1.f / (1.f + expf(-gi));
            float sf = 1.f / (1.f + expf(-gf));
            float so = 1.f / (1.f + expf(-go));
            c = sf * c + si * tanhf(gg);
            float h = so * tanhf(c);
            g_hbuf[(s & 1) * 1024 + j] = h;
            hseq[(size_t)s * hstride + j] = h;
        }
        __syncthreads();
        if (tid == 0)
            asm volatile("red.release.gpu.global.add.u32 [%0], %1;"
                         :: "l"(cnt), "r"(1u) : "memory");
    }
}

// -------------------- guarded (possibly unaligned) float4 load --------------
__device__ __forceinline__ float4 ldg4(const float* __restrict__ base,
                                       int r, int cc, int Rm, int K, int ld) {
    float4 v = make_float4(0.f, 0.f, 0.f, 0.f);
    if (r < Rm) {
        const float* p = base + (size_t)r * ld + cc;
        size_t off = (size_t)r * ld + cc;
        if (cc + 3 < K && ((off & 3u) == 0)) {
            v = *(const float4*)p;
        } else {
            if (cc     < K) v.x = p[0];
            if (cc + 1 < K) v.y = p[1];
            if (cc + 2 < K) v.z = p[2];
            if (cc + 3 < K) v.w = p[3];
        }
    }
    return v;
}

// ------------------------- 64x64 GEMM (small shapes) ------------------------
// C[n][m] = sum_k A[m][k] * B[n][k] (+ b1[m] + b2[m])
__global__ void __launch_bounds__(256) k_gemm(
    const float* __restrict__ A, const float* __restrict__ B,
    float* __restrict__ C, const float* __restrict__ b1, const float* __restrict__ b2,
    int M, int N, int K, int lda, int ldb, int ldc)
{
    __shared__ __align__(16) float As[16][68];
    __shared__ __align__(16) float Bs[16][68];
    int tid = threadIdx.x;
    int m0 = blockIdx.x * 64, n0 = blockIdx.y * 64;
    int lr = tid >> 2, lc = (tid & 3) * 4;
    int tx = tid & 15, ty = tid >> 4;
    float acc[4][4];
#pragma unroll
    for (int i = 0; i < 4; i++)
#pragma unroll
        for (int jj = 0; jj < 4; jj++) acc[i][jj] = 0.f;

    for (int k0 = 0; k0 < K; k0 += 16) {
        float4 a4 = ldg4(A, m0 + lr, k0 + lc, M, K, lda);
        float4 b4 = ldg4(B, n0 + lr, k0 + lc, N, K, ldb);
        As[lc + 0][lr] = a4.x; As[lc + 1][lr] = a4.y;
        As[lc + 2][lr] = a4.z; As[lc + 3][lr] = a4.w;
        Bs[lc + 0][lr] = b4.x; Bs[lc + 1][lr] = b4.y;
        Bs[lc + 2][lr] = b4.z; Bs[lc + 3][lr] = b4.w;
        __syncthreads();
#pragma unroll
        for (int kk = 0; kk < 16; kk++) {
            float4 a = *(const float4*)&As[kk][ty * 4];
            float4 b = *(const float4*)&Bs[kk][tx * 4];
            acc[0][0] += b.x * a.x; acc[0][1] += b.x * a.y; acc[0][2] += b.x * a.z; acc[0][3] += b.x * a.w;
            acc[1][0] += b.y * a.x; acc[1][1] += b.y * a.y; acc[1][2] += b.y * a.z; acc[1][3] += b.y * a.w;
            acc[2][0] += b.z * a.x; acc[2][1] += b.z * a.y; acc[2][2] += b.z * a.z; acc[2][3] += b.z * a.w;
            acc[3][0] += b.w * a.x; acc[3][1] += b.w * a.y; acc[3][2] += b.w * a.z; acc[3][3] += b.w * a.w;
        }
        __syncthreads();
    }

    int mb = m0 + ty * 4;
    float bb[4];
#pragma unroll
    for (int im = 0; im < 4; im++) {
        int m = mb + im;
        bb[im] = (m < M) ? ((b1 ? b1[m] : 0.f) + (b2 ? b2[m] : 0.f)) : 0.f;
    }
#pragma unroll
    for (int jn = 0; jn < 4; jn++) {
        int n = n0 + tx * 4 + jn;
        if (n >= N) continue;
        if (mb + 3 < M) {
            float4 v = make_float4(acc[jn][0] + bb[0], acc[jn][1] + bb[1],
                                   acc[jn][2] + bb[2], acc[jn][3] + bb[3]);
            *(float4*)&C[(size_t)n * ldc + mb] = v;
        } else {
#pragma unroll
            for (int im = 0; im < 4; im++) {
                int m = mb + im;
                if (m < M) C[(size_t)n * ldc + m] = acc[jn][im] + bb[im];
            }
        }
    }
}

// ---------------- 128x128 double-buffered GEMM (big shapes) -----------------
__global__ void __launch_bounds__(256) k_gemm128(
    const float* __restrict__ A, const float* __restrict__ B,
    float* __restrict__ C, const float* __restrict__ b1, const float* __restrict__ b2,
    int M, int N, int K, int lda, int ldb, int ldc)
{
    __shared__ __align__(16) float As[2][8][132];
    __shared__ __align__(16) float Bs[2][8][132];
    int tid = threadIdx.x;
    int m0 = blockIdx.x * 128, n0 = blockIdx.y * 128;
    int lr = tid >> 1;            // 0..127
    int lc = (tid & 1) * 4;       // 0 or 4
    int tx = tid & 15, ty = tid >> 4;

    float acc[8][8];
#pragma unroll
    for (int i = 0; i < 8; i++)
#pragma unroll
        for (int jj = 0; jj < 8; jj++) acc[i][jj] = 0.f;

    // prologue: load k-tile 0 into buffer 0
    {
        float4 a4 = ldg4(A, m0 + lr, lc, M, K, lda);
        float4 b4 = ldg4(B, n0 + lr, lc, N, K, ldb);
        As[0][lc + 0][lr] = a4.x; As[0][lc + 1][lr] = a4.y;
        As[0][lc + 2][lr] = a4.z; As[0][lc + 3][lr] = a4.w;
        Bs[0][lc + 0][lr] = b4.x; Bs[0][lc + 1][lr] = b4.y;
        Bs[0][lc + 2][lr] = b4.z; Bs[0][lc + 3][lr] = b4.w;
    }
    __syncthreads();

    int nk = (K + 7) / 8;
    for (int kt = 0; kt < nk; kt++) {
        int cur = kt & 1, nxt = cur ^ 1;
        float4 a4n, b4n;
        bool more = (kt + 1 < nk);
        if (more) {
            a4n = ldg4(A, m0 + lr, (kt + 1) * 8 + lc, M, K, lda);
            b4n = ldg4(B, n0 + lr, (kt + 1) * 8 + lc, N, K, ldb);
        }
#pragma unroll
        for (int kk = 0; kk < 8; kk++) {
            float4 a0 = *(const float4*)&As[cur][kk][ty * 8];
            float4 a1 = *(const float4*)&As[cur][kk][ty * 8 + 4];
            float4 bb0 = *(const float4*)&Bs[cur][kk][tx * 8];
            float4 bb1 = *(const float4*)&Bs[cur][kk][tx * 8 + 4];
            float av[8] = {a0.x, a0.y, a0.z, a0.w, a1.x, a1.y, a1.z, a1.w};
            float bv[8] = {bb0.x, bb0.y, bb0.z, bb0.w, bb1.x, bb1.y, bb1.z, bb1.w};
#pragma unroll
            for (int i = 0; i < 8; i++)
#pragma unroll
                for (int jj = 0; jj < 8; jj++)
                    acc[i][jj] += av[i] * bv[jj];
        }
        if (more) {
            As[nxt][lc + 0][lr] = a4n.x; As[nxt][lc + 1][lr] = a4n.y;
            As[nxt][lc + 2][lr] = a4n.z; As[nxt][lc + 3][lr] = a4n.w;
            Bs[nxt][lc + 0][lr] = b4n.x; Bs[nxt][lc + 1][lr] = b4n.y;
            Bs[nxt][lc + 2][lr] = b4n.z; Bs[nxt][lc + 3][lr] = b4n.w;
        }
        __syncthreads();
    }

    int mb = m0 + ty * 8;
    float bb[8];
#pragma unroll
    for (int i = 0; i < 8; i++) {
        int m = mb + i;
        bb[i] = (m < M) ? ((b1 ? b1[m] : 0.f) + (b2 ? b2[m] : 0.f)) : 0.f;
    }
#pragma unroll
    for (int jj = 0; jj < 8; jj++) {
        int n = n0 + tx * 8 + jj;
        if (n >= N) continue;
        float* crow = C + (size_t)n * ldc;
        if (mb + 7 < M) {
            float4 v0 = make_float4(acc[0][jj] + bb[0], acc[1][jj] + bb[1],
                                    acc[2][jj] + bb[2], acc[3][jj] + bb[3]);
            float4 v1 = make_float4(acc[4][jj] + bb[4], acc[5][jj] + bb[5],
                                    acc[6][jj] + bb[6], acc[7][jj] + bb[7]);
            *(float4*)&crow[mb]     = v0;
            *(float4*)&crow[mb + 4] = v1;
        } else {
#pragma unroll
            for (int i = 0; i < 8; i++) {
                int m = mb + i;
                if (m < M) crow[m] = acc[i][jj] + bb[i];
            }
        }
    }
}

// ------------------------------ filt ---------------------------------------
__global__ void k_filt(const float* __restrict__ afW, const float* __restrict__ afb) {
    __shared__ float w[1000];
    int cc = blockIdx.x;
    for (int e = threadIdx.x; e < 1000; e += 256) w[e] = afW[(size_t)cc * 1000 + e];
    __syncthreads();
    int t = threadIdx.x >> 5, lane = threadIdx.x & 31;
    float a = 0.f;
    for (int e = lane; e < 1000; e += 32) a += w[e] * g_lo[t * 1000 + e];
    a = wred(a);
    if (lane == 0)
        g_filt[t * 2690 + cc] = 1.f / (1.f + expf(-(a + afb[cc])));
}

// ------------------------------ p (partial + reduce) ------------------------
__global__ void k_ppart() {
    int t = blockIdx.x, ch = blockIdx.y, hw = threadIdx.x;
    int c0 = ch * 128, c1 = min(c0 + 128, 2690);
    const float* f = g_filt + t * 2690;
    float a = 0.f;
    for (int cc = c0; cc < c1; cc++)
        a += f[cc] * g_visxy[cc * 256 + hw];
    g_ppart[(ch * 8 + t) * 256 + hw] = a;
}
__global__ void k_pred() {
    int t = blockIdx.x, hw = threadIdx.x;
    float a = 0.f;
#pragma unroll
    for (int ch = 0; ch < PCH; ch++) a += g_ppart[(ch * 8 + t) * 256 + hw];
    g_p[t * 256 + hw] = a;
}

// ------------------------------ qlang --------------------------------------
__global__ void k_qlang(const float* __restrict__ ccW) {
    int m = blockIdx.x;
    int t = threadIdx.x >> 5, lane = threadIdx.x & 31;
    const float* row = ccW + (size_t)m * 4691;
    float a = 0.f;
    for (int e = lane; e < 1000; e += 32)
        a += row[2690 + e] * g_le[t * 1000 + e] + row[3690 + e] * g_lo[t * 1000 + e];
    a = wred(a);
    if (lane == 0) g_qlang[t * 1000 + m] = a;
}

// ------------------------------ wp / pc ------------------------------------
__global__ void k_wp(const float* __restrict__ Wih0, const float* __restrict__ ccW,
                     const float* __restrict__ ccb, const float* __restrict__ bih,
                     const float* __restrict__ bhh) {
    int r = blockIdx.x * 8 + (threadIdx.x >> 5);
    int lane = threadIdx.x & 31;
    if (r >= 4020) return;
    const float* Wr = Wih0 + (size_t)r * 1000;
    float aw = 0.f, ac = 0.f;
    for (int m = lane; m < 1000; m += 32) {
        float wv = Wr[m];
        aw += wv * ccW[(size_t)m * 4691 + 4690];
        ac += wv * ccb[m];
    }
    aw = wred(aw); ac = wred(ac);
    if (lane == 0) {
        g_wp[r] = aw;
        g_pc[r] = ac + bih[r] + bhh[r];
    }
}

// ------------------------------ pre1 assembly -------------------------------
__global__ void k_pre1() {
    int s = blockIdx.x;
    int t = s & 7, hw = s >> 3;
    float pv = g_p[t * 256 + hw];
    const float* pb = g_PB + (size_t)hw * 4020;
    const float* pl = g_PL + t * 4020;
    float* dst = g_pre + (size_t)s * 4020;
    for (int r = threadIdx.x; r < 4020; r += 256)
        dst[r] = pb[r] + pl[r] + g_wp[r] * pv + g_pc[r];
}

// ------------------------------ out ----------------------------------------
__global__ void k_out(const float* __restrict__ ocW, const float* __restrict__ ocb,
                      float* __restrict__ out) {
    int j = blockIdx.x * 8 + (threadIdx.x >> 5);
    int lane = threadIdx.x & 31;
    const float* h = g_h3 + (size_t)(1792 + j) * HSTR;
    float a = 0.f;
    for (int cc = lane; cc < 1005; cc += 32) a += ocW[cc] * h[cc];
    a = wred(a);
    if (lane == 0) out[j] = a + ocb[0];
}

// ===========================================================================
extern "C" void kernel_launch(void* const* d_in, const int* in_sizes, int n_in,
                              void* d_out, int out_size) {
    const float* vis   = (const float*)d_in[0];
    const int*   lang  = (const int*)  d_in[1];
    const float* emb   = (const float*)d_in[2];
    const float* lWih  = (const float*)d_in[3];
    const float* lWhh  = (const float*)d_in[4];
    const float* lbih  = (const float*)d_in[5];
    const float* lbhh  = (const float*)d_in[6];
    const float* mWih0 = (const float*)d_in[7];
    const float* mWihR = (const float*)d_in[8];
    const float* mWhh  = (const float*)d_in[9];
    const float* mbih  = (const float*)d_in[10];
    const float* mbhh  = (const float*)d_in[11];
    const float* afW   = (const float*)d_in[12];
    const float* afb   = (const float*)d_in[13];
    const float* ccW   = (const float*)d_in[14];
    const float* ccb   = (const float*)d_in[15];
    const float* ocW   = (const float*)d_in[16];
    const float* ocb   = (const float*)d_in[17];
    float* out = (float*)d_out;

    float *pre_, *hl1_, *lo_, *le_, *qlang_, *qbase_, *PB_, *PL_, *visT_, *h1_, *h2_, *h3_;
    unsigned* cnt_;
    cudaGetSymbolAddress((void**)&pre_,   g_pre);
    cudaGetSymbolAddress((void**)&hl1_,   g_hl1);
    cudaGetSymbolAddress((void**)&lo_,    g_lo);
    cudaGetSymbolAddress((void**)&le_,    g_le);
    cudaGetSymbolAddress((void**)&qlang_, g_qlang);
    cudaGetSymbolAddress((void**)&qbase_, g_qbase);
    cudaGetSymbolAddress((void**)&PB_,    g_PB);
    cudaGetSymbolAddress((void**)&PL_,    g_PL);
    cudaGetSymbolAddress((void**)&visT_,  g_visxyT);
    cudaGetSymbolAddress((void**)&h1_,    g_h1);
    cudaGetSymbolAddress((void**)&h2_,    g_h2);
    cudaGetSymbolAddress((void**)&h3_,    g_h3);
    cudaGetSymbolAddress((void**)&cnt_,   g_cnt);

    auto gemm = [](const float* A, const float* B, float* C,
                   const float* b1, const float* b2,
                   int M, int N, int K, int lda, int ldb, int ldc) {
        dim3 g((M + 63) / 64, (N + 63) / 64);
        k_gemm<<<g, 256>>>(A, B, C, b1, b2, M, N, K, lda, ldb, ldc);
    };
    auto gemm128 = [](const float* A, const float* B, float* C,
                      const float* b1, const float* b2,
                      int M, int N, int K, int lda, int ldb, int ldc) {
        dim3 g((M + 127) / 128, (N + 127) / 128);
        k_gemm128<<<g, 256>>>(A, B, C, b1, b2, M, N, K, lda, ldb, ldc);
    };

    k_init<<<1, 32>>>();
    k_visxy<<<2690, 256>>>(vis);
    k_embed<<<8, 256>>>(lang, emb);

    // ---- language LSTM (2 layers, T=8, Hn=1000) ----
    gemm(lWih, le_, pre_, lbih, lbhh, 4000, 8, 1000, 1000, 1000, 4000);
    k_scan<<<125, 256>>>(pre_, lWhh, hl1_, 1000, cnt_ + 0, 8, 1000);
    gemm(lWih + 4000000, hl1_, pre_, lbih + 4000, lbhh + 4000, 4000, 8, 1000, 1000, 1000, 4000);
    k_scan<<<125, 256>>>(pre_, lWhh + 4000000, lo_, 1000, cnt_ + 1, 8, 1000);

    // ---- attention filter + q decomposition ----
    k_filt<<<2690, 256>>>(afW, afb);
    k_ppart<<<dim3(8, PCH), 256>>>();
    k_pred<<<8, 256>>>();
    k_qlang<<<1000, 256>>>(ccW);
    gemm(ccW, visT_, qbase_, nullptr, nullptr, 1000, 256, 2690, 4691, 2690, 1000);
    gemm(mWih0, qbase_, PB_, nullptr, nullptr, 4020, 256, 1000, 1000, 1000, 4020);
    gemm(mWih0, qlang_, PL_, nullptr, nullptr, 4020, 8, 1000, 1000, 1000, 4020);
    k_wp<<<503, 256>>>(mWih0, ccW, ccb, mbih, mbhh);
    k_pre1<<<2048, 256>>>();

    // ---- mRNN (3 layers, T=2048, Hn=1005) ----
    k_scan<<<126, 256>>>(pre_, mWhh, h1_, HSTR, cnt_ + 2, 2048, 1005);
    gemm128(mWihR, h1_, pre_, mbih + 4020, mbhh + 4020, 4020, 2048, 1005, 1005, HSTR, 4020);
    k_scan<<<126, 256>>>(pre_, mWhh + (size_t)4020 * 1005, h2_, HSTR, cnt_ + 3, 2048, 1005);
    gemm128(mWihR + (size_t)4020 * 1005, h2_, pre_, mbih + 8040, mbhh + 8040, 4020, 2048, 1005, 1005, HSTR, 4020);
    k_scan<<<126, 256>>>(pre_, mWhh + (size_t)2 * 4020 * 1005, h3_, HSTR, cnt_ + 4, 2048, 1005);

    // ---- final projection ----
    k_out<<<32, 256>>>(ocW, ocb, out);
}